// round 12
// baseline (speedup 1.0000x reference)
#include <cuda_runtime.h>
#include <cuda_bf16.h>
#include <cstdint>

// Problem constants (fixed shapes)
#define BATCH 2
#define CDIM 128
#define NPIX 65536          // 256*256
#define LAST0 64512         // (chunks-1)*M
#define SCALE_L2 20.6099075f   // 1/(0.07 * ln2)
#define LN2F 0.6931471805599453f

typedef unsigned long long u64;

// ---------------- scratch (device globals: no allocations allowed) ----------
__device__ uint4    g_Bpack[BATCH * 16 * 1024];   // 512 KB: [b][it][(nb*4+s2)*32+lane]
__device__ float    g_bscale[BATCH * 1024];       // SCALE_L2 * inv2 per last-chunk col
__device__ double   g_acc;
__device__ unsigned g_done;

// ---------------- helpers ----------------
__device__ __forceinline__ unsigned pack2(float lo, float hi) {
    __nv_bfloat162 h = __floats2bfloat162_rn(lo, hi);
    return *reinterpret_cast<unsigned*>(&h);
}
__device__ __forceinline__ u64 pk(float lo, float hi) {
    u64 r; asm("mov.b64 %0,{%1,%2};" : "=l"(r) : "f"(lo), "f"(hi)); return r;
}
__device__ __forceinline__ u64 bc(float x) {
    u64 r; asm("mov.b64 %0,{%1,%1};" : "=l"(r) : "f"(x)); return r;
}
__device__ __forceinline__ u64 fma2(u64 a, u64 b, u64 c) {
    u64 d; asm("fma.rn.f32x2 %0,%1,%2,%3;" : "=l"(d) : "l"(a), "l"(b), "l"(c)); return d;
}
__device__ __forceinline__ u64 add2(u64 a, u64 b) {
    u64 d; asm("add.rn.f32x2 %0,%1,%2;" : "=l"(d) : "l"(a), "l"(b)); return d;
}
__device__ __forceinline__ u64 sub2(u64 a, u64 b) {
    u64 d; asm("sub.rn.f32x2 %0,%1,%2;" : "=l"(d) : "l"(a), "l"(b)); return d;
}
// scalar exp2 (pos only). Exact at x==0.
__device__ __forceinline__ float exp2p(float x) {
    int   i = __float2int_rn(x);
    float f = x - (float)i;
    float p = 9.6181291076e-3f;
    p = fmaf(p, f, 5.5504108664e-2f);
    p = fmaf(p, f, 2.4022650696e-1f);
    p = fmaf(p, f, 6.9314718056e-1f);
    p = fmaf(p, f, 1.0f);
    return __int_as_float(__float_as_int(p) + (i << 23));
}
// unpack bf16x2, scale both halves by f (fp32), repack
__device__ __forceinline__ unsigned scl2(unsigned u, float f) {
    float lo = __int_as_float(u << 16) * f;
    float hi = __int_as_float(u & 0xFFFF0000u) * f;
    return pack2(lo, hi);
}

#define CP16(dst, src) asm volatile("cp.async.ca.shared.global [%0],[%1],16;\n" :: "r"(dst), "l"(src))
#define CPCOMMIT()     asm volatile("cp.async.commit_group;\n")
#define CPWAIT0()      asm volatile("cp.async.wait_group 0;\n")

#define MMA_BF16(c0, c1, c2, c3, av, b0, b1)                               \
    asm volatile(                                                           \
        "mma.sync.aligned.m16n8k16.row.col.f32.bf16.bf16.f32 "             \
        "{%0,%1,%2,%3}, {%4,%5,%6,%7}, {%8,%9}, {%0,%1,%2,%3};\n"          \
        : "+f"(c0), "+f"(c1), "+f"(c2), "+f"(c3)                            \
        : "r"((av).x), "r"((av).y), "r"((av).z), "r"((av).w),               \
          "r"(b0), "r"(b1))

// packed exp2 accumulate: sep += exp2(P) elementwise (deg-3 Taylor, exact at 0)
#define EXP2ACC(sep, P) do {                                                \
    u64 t  = add2(P, MAG);                                                  \
    u64 ii = sub2(t, MAG);                                                  \
    u64 f  = sub2(P, ii);                                                   \
    u64 p  = fma2(C3, f, C2);                                               \
    p = fma2(p, f, C1); p = fma2(p, f, ONE);                                \
    unsigned t0, t1, q0, q1;                                                \
    asm("mov.b64 {%0,%1},%2;" : "=r"(t0), "=r"(t1) : "l"(t));               \
    asm("mov.b64 {%0,%1},%2;" : "=r"(q0), "=r"(q1) : "l"(p));               \
    q0 += t0 << 23; q1 += t1 << 23;                                         \
    u64 e; asm("mov.b64 %0,{%1,%2};" : "=l"(e) : "r"(q0), "r"(q1));         \
    sep = add2(sep, e);                                                     \
} while (0)

// epilogue on saved (already merged) results c[8] with label pair lcp
#define EPILOGUE(c, lcp) do {                                               \
    u64 P0 = pk((lr0 != (lcp).x) ? (c)[0] : 0.f, (lr0 != (lcp).y) ? (c)[1] : 0.f); \
    u64 P1 = pk((lr1 != (lcp).x) ? (c)[2] : 0.f, (lr1 != (lcp).y) ? (c)[3] : 0.f); \
    u64 P2 = pk((lr2 != (lcp).x) ? (c)[4] : 0.f, (lr2 != (lcp).y) ? (c)[5] : 0.f); \
    u64 P3 = pk((lr3 != (lcp).x) ? (c)[6] : 0.f, (lr3 != (lcp).y) ? (c)[7] : 0.f); \
    sxp = add2(sxp, add2(add2(P0, P1), add2(P2, P3)));                      \
    EXP2ACC(sep0, P0);                                                      \
    EXP2ACC(sep1, P1);                                                      \
    EXP2ACC(sep2, P2);                                                      \
    EXP2ACC(sep3, P3);                                                      \
} while (0)

// ---------------- kernel 1: column norms of last-chunk z2 ----------------
__global__ void __launch_bounds__(256) k_colnorm(const float* __restrict__ z2) {
    int g = blockIdx.x * 256 + threadIdx.x;     // 0..2047
    if (g == 0) { g_acc = 0.0; g_done = 0u; }
    int b = g >> 10, col = g & 1023;
    const float* zp = z2 + (size_t)b * CDIM * NPIX + LAST0 + col;
    float ss = 0.f;
#pragma unroll 8
    for (int c = 0; c < CDIM; c++) {
        float v = zp[(size_t)c * NPIX];
        ss = fmaf(v, v, ss);
    }
    g_bscale[g] = SCALE_L2 / fmaxf(sqrtf(ss), 1e-12f);
}

// ---------------- kernel 2: pack B fragments as uint4 (2 k-steps per entry) --------
__global__ void __launch_bounds__(256) k_packB(const float* __restrict__ z2) {
    int g = blockIdx.x * 256 + threadIdx.x;       // 0..32767
    int b   = g >> 14;
    int r   = g & 16383;
    int it  = r >> 10;
    int idx = r & 1023;
    int nb  = idx >> 7;
    int s2  = (idx >> 5) & 3;
    int lane = idx & 31;
    int gid = lane >> 2, tig = lane & 3;
    int col = it * 64 + nb * 8 + gid;
    float inv = g_bscale[b * 1024 + col];
    const float* zp = z2 + (size_t)b * CDIM * NPIX + LAST0 + col;
    int k0 = s2 * 32 + tig * 2;
    uint4 o;
    o.x = pack2(zp[(size_t)(k0     ) * NPIX] * inv, zp[(size_t)(k0 +  1) * NPIX] * inv);
    o.y = pack2(zp[(size_t)(k0 +  8) * NPIX] * inv, zp[(size_t)(k0 +  9) * NPIX] * inv);
    o.z = pack2(zp[(size_t)(k0 + 16) * NPIX] * inv, zp[(size_t)(k0 + 17) * NPIX] * inv);
    o.w = pack2(zp[(size_t)(k0 + 24) * NPIX] * inv, zp[(size_t)(k0 + 25) * NPIX] * inv);
    g_Bpack[g] = o;
}

// ---------------- kernel 3: fused norm + bf16 GEMM + epilogue + finalize ------------
__global__ void __launch_bounds__(128, 3) k_main(const float* __restrict__ z1,
                                                 const float* __restrict__ z2,
                                                 const int* __restrict__ labels,
                                                 float* __restrict__ out) {
    const int b    = blockIdx.y;
    const int row0 = blockIdx.x * 128;
    const int tid  = threadIdx.x;      // 0..127
    const int w    = tid >> 5;         // 0..3
    const int lane = tid & 31;
    const int gid  = lane >> 2, tig = lane & 3;

    __shared__ uint4 Bsm[2][1024];   // double-buffered 16KB B tiles (prologue: A stage)
    __shared__ int   labsm[1024];
    __shared__ float warpsum[4];

    // ---- prologue: normalize this warp's 32 pixels, build A fragments in regs ----
    // lane owns pixel row0 + w*32 + lane; stage raw z1 as bf16 pairs in Bsm region.
    uint4 a0[8], a1[8];
    float mypos;
    {
        const size_t base = (size_t)b * CDIM * NPIX + row0 + w * 32 + lane;
        const float* z1p = z1 + base;
        const float* z2p = z2 + base;
        unsigned* stg = reinterpret_cast<unsigned*>(&Bsm[0][0]) + w * 2048;
        float ss1 = 0.f, ss2 = 0.f, dt = 0.f;
#pragma unroll 8
        for (int c2 = 0; c2 < 64; c2++) {
            float v1a = z1p[(size_t)(2 * c2    ) * NPIX];
            float v1b = z1p[(size_t)(2 * c2 + 1) * NPIX];
            float v2a = z2p[(size_t)(2 * c2    ) * NPIX];
            float v2b = z2p[(size_t)(2 * c2 + 1) * NPIX];
            ss1 = fmaf(v1a, v1a, ss1); ss1 = fmaf(v1b, v1b, ss1);
            ss2 = fmaf(v2a, v2a, ss2); ss2 = fmaf(v2b, v2b, ss2);
            dt  = fmaf(v1a, v2a, dt);  dt  = fmaf(v1b, v2b, dt);
            stg[c2 * 32 + lane] = pack2(v1a, v1b);
        }
        float inv1 = 1.f / fmaxf(sqrtf(ss1), 1e-12f);
        float inv2 = 1.f / fmaxf(sqrtf(ss2), 1e-12f);
        mypos = dt * inv1 * inv2 * SCALE_L2;   // pos logit in log2 domain
        __syncwarp();
        // inv1 of the 4 pixels this lane's fragments touch
        float ig   = __shfl_sync(~0u, inv1, gid);
        float ig8  = __shfl_sync(~0u, inv1, gid + 8);
        float ig16 = __shfl_sync(~0u, inv1, gid + 16);
        float ig24 = __shfl_sync(~0u, inv1, gid + 24);
#pragma unroll
        for (int s = 0; s < 8; s++) {
            int r0i = (s * 8 + tig) * 32;
            int r1i = (s * 8 + tig + 4) * 32;
            a0[s].x = scl2(stg[r0i + gid     ], ig);
            a0[s].y = scl2(stg[r0i + gid + 8 ], ig8);
            a0[s].z = scl2(stg[r1i + gid     ], ig);
            a0[s].w = scl2(stg[r1i + gid + 8 ], ig8);
            a1[s].x = scl2(stg[r0i + gid + 16], ig16);
            a1[s].y = scl2(stg[r0i + gid + 24], ig24);
            a1[s].z = scl2(stg[r1i + gid + 16], ig16);
            a1[s].w = scl2(stg[r1i + gid + 24], ig24);
        }
    }
    __syncthreads();   // stage region fully consumed; Bsm free for B tiles

    // labels of last chunk -> shared (vectorized, 128 threads x 2)
    {
        const uint4* lp = (const uint4*)(labels + b * NPIX + LAST0);
        ((uint4*)labsm)[tid]       = lp[tid];
        ((uint4*)labsm)[tid + 128] = lp[tid + 128];
    }

    const int r0  = row0 + w * 32 + gid;
    const int lr0 = labels[b * NPIX + r0];
    const int lr1 = labels[b * NPIX + r0 + 8];
    const int lr2 = labels[b * NPIX + r0 + 16];
    const int lr3 = labels[b * NPIX + r0 + 24];

    // packed constants
    const u64 MAG = bc(12582912.0f);   // 1.5 * 2^23
    const u64 C3 = bc(5.5504108664e-2f);
    const u64 C2 = bc(2.4022650696e-1f);
    const u64 C1 = bc(6.9314718056e-1f);
    const u64 ONE = bc(1.0f);

    u64 sxp = 0;                                   // warp-global sum of masked logits
    u64 sep0 = 0, sep1 = 0, sep2 = 0, sep3 = 0;    // per-row-pair exp sums

    // 4 independent mma chains + pipelined saved results
    float eA0=0.f,eA1=0.f,eA2=0.f,eA3=0.f, oA0=0.f,oA1=0.f,oA2=0.f,oA3=0.f;
    float eB0=0.f,eB1=0.f,eB2=0.f,eB3=0.f, oB0=0.f,oB1=0.f,oB2=0.f,oB3=0.f;
    float csv[8];
    int2  lcp = make_int2(0, 0);

    const uint4* Bp = g_Bpack + b * 16384;

    // prefetch tile 0 (1024 uint4 by 128 threads)
    {
        unsigned sd = (unsigned)__cvta_generic_to_shared(&Bsm[0][0]);
#pragma unroll
        for (int i = 0; i < 8; i++)
            CP16(sd + (tid + 128 * i) * 16, Bp + tid + 128 * i);
        CPCOMMIT();
    }

    for (int it = 0; it < 16; it++) {
        const int buf = it & 1;
        CPWAIT0();
        __syncthreads();
        if (it < 15) {
            unsigned sd = (unsigned)__cvta_generic_to_shared(&Bsm[buf ^ 1][0]);
            const uint4* src = Bp + (it + 1) * 1024;
#pragma unroll
            for (int i = 0; i < 8; i++)
                CP16(sd + (tid + 128 * i) * 16, src + tid + 128 * i);
            CPCOMMIT();
        }

        const uint4* Bb = &Bsm[buf][0];
#pragma unroll
        for (int nb = 0; nb < 8; nb++) {
            // (1) merge previous nb's chains into saved regs (results long ready)
            if (it + nb > 0) {
                csv[0] = eA0 + oA0; csv[1] = eA1 + oA1;
                csv[2] = eA2 + oA2; csv[3] = eA3 + oA3;
                csv[4] = eB0 + oB0; csv[5] = eB1 + oB1;
                csv[6] = eB2 + oB2; csv[7] = eB3 + oB3;
            }
            // (2) issue this nb's 16 mmas into the freed chains
            eA0=0.f;eA1=0.f;eA2=0.f;eA3=0.f; oA0=0.f;oA1=0.f;oA2=0.f;oA3=0.f;
            eB0=0.f;eB1=0.f;eB2=0.f;eB3=0.f; oB0=0.f;oB1=0.f;oB2=0.f;oB3=0.f;
#pragma unroll
            for (int s2 = 0; s2 < 4; s2++) {
                uint4 bf = Bb[(nb * 4 + s2) * 32 + lane];
                MMA_BF16(eA0, eA1, eA2, eA3, a0[2 * s2],     bf.x, bf.y);
                MMA_BF16(eB0, eB1, eB2, eB3, a1[2 * s2],     bf.x, bf.y);
                MMA_BF16(oA0, oA1, oA2, oA3, a0[2 * s2 + 1], bf.z, bf.w);
                MMA_BF16(oB0, oB1, oB2, oB3, a1[2 * s2 + 1], bf.z, bf.w);
            }
            // (3) epilogue for the previous nb while these mmas are in flight
            if (it + nb > 0) EPILOGUE(csv, lcp);
            // (4) capture this nb's column labels for next round
            lcp = ((const int2*)labsm)[it * 32 + nb * 4 + tig];
        }
        __syncthreads();   // all reads of buf done before next prefetch overwrites
    }

    // drain: merge + epilogue for the final nb
    csv[0] = eA0 + oA0; csv[1] = eA1 + oA1;
    csv[2] = eA2 + oA2; csv[3] = eA3 + oA3;
    csv[4] = eB0 + oB0; csv[5] = eB1 + oB1;
    csv[6] = eB2 + oB2; csv[7] = eB3 + oB3;
    EPILOGUE(csv, lcp);

    // unpack packed accumulators
    float sa, sb;
    asm("mov.b64 {%0,%1},%2;" : "=f"(sa), "=f"(sb) : "l"(sxp));  float sxw = sa + sb;
    asm("mov.b64 {%0,%1},%2;" : "=f"(sa), "=f"(sb) : "l"(sep0)); float se0 = sa + sb;
    asm("mov.b64 {%0,%1},%2;" : "=f"(sa), "=f"(sb) : "l"(sep1)); float se1 = sa + sb;
    asm("mov.b64 {%0,%1},%2;" : "=f"(sa), "=f"(sb) : "l"(sep2)); float se2 = sa + sb;
    asm("mov.b64 {%0,%1},%2;" : "=f"(sa), "=f"(sb) : "l"(sep3)); float se3 = sa + sb;

    // per-row exp sums: reduce across the 4 lanes sharing each row
#pragma unroll
    for (int o = 1; o <= 2; o <<= 1) {
        se0 += __shfl_xor_sync(~0u, se0, o);
        se1 += __shfl_xor_sync(~0u, se1, o);
        se2 += __shfl_xor_sync(~0u, se2, o);
        se3 += __shfl_xor_sync(~0u, se3, o);
    }

    // recover pos logits for this thread's 4 rows from lane-resident mypos
    float p0 = __shfl_sync(~0u, mypos, gid);
    float p1 = __shfl_sync(~0u, mypos, gid + 8);
    float p2 = __shfl_sync(~0u, mypos, gid + 16);
    float p3 = __shfl_sync(~0u, mypos, gid + 24);

    float v = 0.f;
    if (tig == 0) {
        float t0 = se0 + exp2p(p0);
        float t1 = se1 + exp2p(p1);
        float t2 = se2 + exp2p(p2);
        float t3 = se3 + exp2p(p3);
        v = (__log2f(t0) + __log2f(t1) + __log2f(t2) + __log2f(t3))
            - (p0 + p1 + p2 + p3) * (1.0f / 1025.0f);
    }
    v -= sxw * (1.0f / 1025.0f / 32.0f);   // spread warp-global sx over 32 lanes
#pragma unroll
    for (int o = 16; o; o >>= 1) v += __shfl_xor_sync(~0u, v, o);
    if (lane == 0) warpsum[w] = LN2F * v;
    __syncthreads();
    if (tid == 0) {
        float ts = warpsum[0] + warpsum[1] + warpsum[2] + warpsum[3];
        atomicAdd(&g_acc, (double)ts);
        __threadfence();
        unsigned done = atomicAdd(&g_done, 1u) + 1u;
        if (done == gridDim.x * gridDim.y) {
            double total = atomicAdd(&g_acc, 0.0);   // coherent read after all adds
            out[0] = (float)(total / (double)(BATCH * NPIX));
        }
    }
}

// ---------------- launch ----------------
extern "C" void kernel_launch(void* const* d_in, const int* in_sizes, int n_in,
                              void* d_out, int out_size) {
    const float* z1     = (const float*)d_in[0];
    const float* z2     = (const float*)d_in[1];
    const int*   labels = (const int*)d_in[2];
    (void)in_sizes; (void)n_in; (void)out_size;

    k_colnorm<<<8, 256>>>(z2);
    k_packB<<<128, 256>>>(z2);
    dim3 g2(NPIX / 128, BATCH);
    k_main<<<g2, 128>>>(z1, z2, labels, (float*)d_out);
}

// round 13
// speedup vs baseline: 1.1910x; 1.1910x over previous
#include <cuda_runtime.h>
#include <cuda_bf16.h>
#include <cstdint>

// Problem constants (fixed shapes)
#define BATCH 2
#define CDIM 128
#define NPIX 65536          // 256*256
#define LAST0 64512         // (chunks-1)*M
#define NROWBLK 4096        // NPIX/16
#define SCALE_L2 20.6099075f   // 1/(0.07 * ln2)
#define LN2F 0.6931471805599453f

typedef unsigned long long u64;

// ---------------- scratch (device globals: no allocations allowed) ----------
__device__ uint4    g_Apack[BATCH * NROWBLK * 8 * 32];   // 33.5 MB, bf16 mma A fragments
__device__ uint4    g_Bpack[BATCH * 16 * 1024];          // 512 KB: [b][it][(nb*4+s2)*32+lane]
__device__ float    g_inv2[BATCH * NPIX];
__device__ float    g_posl2[BATCH * NPIX];               // pos logit in log2 domain
__device__ double   g_acc;
__device__ unsigned g_done;

// ---------------- helpers ----------------
__device__ __forceinline__ unsigned pack2(float lo, float hi) {
    __nv_bfloat162 h = __floats2bfloat162_rn(lo, hi);
    return *reinterpret_cast<unsigned*>(&h);
}
__device__ __forceinline__ u64 pk(float lo, float hi) {
    u64 r; asm("mov.b64 %0,{%1,%2};" : "=l"(r) : "f"(lo), "f"(hi)); return r;
}
__device__ __forceinline__ u64 bc(float x) {
    u64 r; asm("mov.b64 %0,{%1,%1};" : "=l"(r) : "f"(x)); return r;
}
__device__ __forceinline__ u64 fma2(u64 a, u64 b, u64 c) {
    u64 d; asm("fma.rn.f32x2 %0,%1,%2,%3;" : "=l"(d) : "l"(a), "l"(b), "l"(c)); return d;
}
__device__ __forceinline__ u64 add2(u64 a, u64 b) {
    u64 d; asm("add.rn.f32x2 %0,%1,%2;" : "=l"(d) : "l"(a), "l"(b)); return d;
}
__device__ __forceinline__ u64 sub2(u64 a, u64 b) {
    u64 d; asm("sub.rn.f32x2 %0,%1,%2;" : "=l"(d) : "l"(a), "l"(b)); return d;
}
// scalar exp2 (pos only). Exact at x==0.
__device__ __forceinline__ float exp2p(float x) {
    int   i = __float2int_rn(x);
    float f = x - (float)i;
    float p = 9.6181291076e-3f;
    p = fmaf(p, f, 5.5504108664e-2f);
    p = fmaf(p, f, 2.4022650696e-1f);
    p = fmaf(p, f, 6.9314718056e-1f);
    p = fmaf(p, f, 1.0f);
    return __int_as_float(__float_as_int(p) + (i << 23));
}

#define CP16(dst, src) asm volatile("cp.async.ca.shared.global [%0],[%1],16;\n" :: "r"(dst), "l"(src))
#define CPCOMMIT()     asm volatile("cp.async.commit_group;\n")
#define CPWAIT0()      asm volatile("cp.async.wait_group 0;\n")

#define MMA_BF16(c0, c1, c2, c3, av, b0, b1)                               \
    asm volatile(                                                           \
        "mma.sync.aligned.m16n8k16.row.col.f32.bf16.bf16.f32 "             \
        "{%0,%1,%2,%3}, {%4,%5,%6,%7}, {%8,%9}, {%0,%1,%2,%3};\n"          \
        : "+f"(c0), "+f"(c1), "+f"(c2), "+f"(c3)                            \
        : "r"((av).x), "r"((av).y), "r"((av).z), "r"((av).w),               \
          "r"(b0), "r"(b1))

// packed exp2 accumulate: sep += exp2(P) elementwise (deg-3 Taylor, exact at 0)
#define EXP2ACC(sep, P) do {                                                \
    u64 t  = add2(P, MAG);                                                  \
    u64 ii = sub2(t, MAG);                                                  \
    u64 f  = sub2(P, ii);                                                   \
    u64 p  = fma2(C3, f, C2);                                               \
    p = fma2(p, f, C1); p = fma2(p, f, ONE);                                \
    unsigned t0, t1, q0, q1;                                                \
    asm("mov.b64 {%0,%1},%2;" : "=r"(t0), "=r"(t1) : "l"(t));               \
    asm("mov.b64 {%0,%1},%2;" : "=r"(q0), "=r"(q1) : "l"(p));               \
    q0 += t0 << 23; q1 += t1 << 23;                                         \
    u64 e; asm("mov.b64 %0,{%1,%2};" : "=l"(e) : "r"(q0), "r"(q1));         \
    sep = add2(sep, e);                                                     \
} while (0)

// epilogue on saved (already merged) results c[8] with label pair lcp
#define EPILOGUE(c, lcp) do {                                               \
    u64 P0 = pk((lr0 != (lcp).x) ? (c)[0] : 0.f, (lr0 != (lcp).y) ? (c)[1] : 0.f); \
    u64 P1 = pk((lr1 != (lcp).x) ? (c)[2] : 0.f, (lr1 != (lcp).y) ? (c)[3] : 0.f); \
    u64 P2 = pk((lr2 != (lcp).x) ? (c)[4] : 0.f, (lr2 != (lcp).y) ? (c)[5] : 0.f); \
    u64 P3 = pk((lr3 != (lcp).x) ? (c)[6] : 0.f, (lr3 != (lcp).y) ? (c)[7] : 0.f); \
    sxp = add2(sxp, add2(add2(P0, P1), add2(P2, P3)));                      \
    EXP2ACC(sep0, P0);                                                      \
    EXP2ACC(sep1, P1);                                                      \
    EXP2ACC(sep2, P2);                                                      \
    EXP2ACC(sep3, P3);                                                      \
} while (0)

// ---------------- kernel 1: normalize z1/z2, pos (fp32), pack A fragments ----------
__global__ void __launch_bounds__(256) k_norm_pack(const float* __restrict__ z1,
                                                   const float* __restrict__ z2) {
    if (blockIdx.x == 0 && blockIdx.y == 0 && threadIdx.x == 0) {
        g_acc = 0.0;
        g_done = 0u;
    }
    const int b  = blockIdx.y;
    const int p0 = blockIdx.x * 32;
    const int tx = threadIdx.x & 31;   // pixel within tile
    const int ty = threadIdx.x >> 5;   // channel group

    __shared__ float s1[128][33];
    __shared__ float red[3][8][32];
    __shared__ float invsm[32];

    const float* z1b = z1 + (size_t)b * CDIM * NPIX + p0;
    const float* z2b = z2 + (size_t)b * CDIM * NPIX + p0;

    float ss1 = 0.f, ss2 = 0.f, dt = 0.f;
#pragma unroll
    for (int j = 0; j < 16; j++) {
        int c = ty * 16 + j;
        float v1 = z1b[(size_t)c * NPIX + tx];
        float v2 = z2b[(size_t)c * NPIX + tx];
        ss1 = fmaf(v1, v1, ss1);
        ss2 = fmaf(v2, v2, ss2);
        dt  = fmaf(v1, v2, dt);
        s1[c][tx] = v1;
    }
    red[0][ty][tx] = ss1; red[1][ty][tx] = ss2; red[2][ty][tx] = dt;
    __syncthreads();

    if (ty == 0) {
        float a = 0.f, bb = 0.f, d = 0.f;
#pragma unroll
        for (int j = 0; j < 8; j++) { a += red[0][j][tx]; bb += red[1][j][tx]; d += red[2][j][tx]; }
        float inv1 = 1.f / fmaxf(sqrtf(a),  1e-12f);
        float inv2 = 1.f / fmaxf(sqrtf(bb), 1e-12f);
        invsm[tx] = inv1;
        g_inv2 [b * NPIX + p0 + tx] = inv2;
        g_posl2[b * NPIX + p0 + tx] = d * inv1 * inv2 * SCALE_L2;  // pos in log2 domain
    }
    __syncthreads();

    // Pack A into mma fragment order
#pragma unroll
    for (int q = 0; q < 2; q++) {
        int wi   = threadIdx.x + q * 256;
        int rbl  = wi >> 8;
        int rem  = wi & 255;
        int s    = rem >> 5;
        int lane = rem & 31;
        int gid  = lane >> 2, tig = lane & 3;
        int pl   = rbl * 16 + gid;
        int k0   = s * 16 + tig * 2;
        float i1 = invsm[pl], i2 = invsm[pl + 8];
        uint4 o;
        o.x = pack2(s1[k0    ][pl]     * i1, s1[k0 + 1][pl]     * i1);
        o.y = pack2(s1[k0    ][pl + 8] * i2, s1[k0 + 1][pl + 8] * i2);
        o.z = pack2(s1[k0 + 8][pl]     * i1, s1[k0 + 9][pl]     * i1);
        o.w = pack2(s1[k0 + 8][pl + 8] * i2, s1[k0 + 9][pl + 8] * i2);
        int rb = blockIdx.x * 2 + rbl;
        g_Apack[((b * NROWBLK + rb) * 8 + s) * 32 + lane] = o;
    }
}

// ---------------- kernel 2: pack B fragments as uint4 (2 k-steps per entry) --------
__global__ void __launch_bounds__(256) k_packB(const float* __restrict__ z2) {
    int g = blockIdx.x * 256 + threadIdx.x;       // 0..32767
    int b   = g >> 14;
    int r   = g & 16383;
    int it  = r >> 10;
    int idx = r & 1023;
    int nb  = idx >> 7;
    int s2  = (idx >> 5) & 3;
    int lane = idx & 31;
    int gid = lane >> 2, tig = lane & 3;
    int n  = nb * 8 + gid;
    int pq = LAST0 + it * 64 + n;
    float inv = g_inv2[b * NPIX + pq] * SCALE_L2;
    const float* zp = z2 + (size_t)b * CDIM * NPIX + pq;
    int k0 = s2 * 32 + tig * 2;
    uint4 o;
    o.x = pack2(zp[(size_t)(k0     ) * NPIX] * inv, zp[(size_t)(k0 +  1) * NPIX] * inv);
    o.y = pack2(zp[(size_t)(k0 +  8) * NPIX] * inv, zp[(size_t)(k0 +  9) * NPIX] * inv);
    o.z = pack2(zp[(size_t)(k0 + 16) * NPIX] * inv, zp[(size_t)(k0 + 17) * NPIX] * inv);
    o.w = pack2(zp[(size_t)(k0 + 24) * NPIX] * inv, zp[(size_t)(k0 + 25) * NPIX] * inv);
    g_Bpack[g] = o;
}

// ---------------- kernel 3: bf16 GEMM + fused epilogue + folded finalize ------------
__global__ void __launch_bounds__(128, 3) k_main(const int* __restrict__ labels,
                                                 float* __restrict__ out) {
    const int b    = blockIdx.y;
    const int row0 = blockIdx.x * 128;
    const int tid  = threadIdx.x;      // 0..127
    const int w    = tid >> 5;         // 0..3
    const int lane = tid & 31;
    const int gid  = lane >> 2, tig = lane & 3;

    __shared__ uint4 Bsm[2][1024];   // double-buffered 16KB B tiles
    __shared__ int   labsm[1024];
    __shared__ float warpsum[4];

    // labels of last chunk -> shared (vectorized, 128 threads x 2)
    {
        const uint4* lp = (const uint4*)(labels + b * NPIX + LAST0);
        ((uint4*)labsm)[tid]       = lp[tid];
        ((uint4*)labsm)[tid + 128] = lp[tid + 128];
    }

    // A fragments for this warp's 32 rows (2 rowblocks): 16 x uint4
    const int rb0 = blockIdx.x * 8 + w * 2;
    uint4 a0[8], a1[8];
    const uint4* Ap = g_Apack + ((size_t)(b * NROWBLK + rb0) * 8) * 32 + lane;
#pragma unroll
    for (int s = 0; s < 8; s++) { a0[s] = Ap[s * 32]; a1[s] = Ap[256 + s * 32]; }

    const int r0  = row0 + w * 32 + gid;
    const int lr0 = labels[b * NPIX + r0];
    const int lr1 = labels[b * NPIX + r0 + 8];
    const int lr2 = labels[b * NPIX + r0 + 16];
    const int lr3 = labels[b * NPIX + r0 + 24];

    // packed constants
    const u64 MAG = bc(12582912.0f);   // 1.5 * 2^23
    const u64 C3 = bc(5.5504108664e-2f);
    const u64 C2 = bc(2.4022650696e-1f);
    const u64 C1 = bc(6.9314718056e-1f);
    const u64 ONE = bc(1.0f);

    u64 sxp = 0;                                   // warp-global sum of masked logits
    u64 sep0 = 0, sep1 = 0, sep2 = 0, sep3 = 0;    // per-row-pair exp sums

    // 4 independent mma chains + pipelined saved results
    float eA0=0.f,eA1=0.f,eA2=0.f,eA3=0.f, oA0=0.f,oA1=0.f,oA2=0.f,oA3=0.f;
    float eB0=0.f,eB1=0.f,eB2=0.f,eB3=0.f, oB0=0.f,oB1=0.f,oB2=0.f,oB3=0.f;
    float csv[8];
    int2  lcp = make_int2(0, 0);

    const uint4* Bp = g_Bpack + b * 16384;

    // prefetch tile 0 (1024 uint4 by 128 threads)
    {
        unsigned sd = (unsigned)__cvta_generic_to_shared(&Bsm[0][0]);
#pragma unroll
        for (int i = 0; i < 8; i++)
            CP16(sd + (tid + 128 * i) * 16, Bp + tid + 128 * i);
        CPCOMMIT();
    }

    for (int it = 0; it < 16; it++) {
        const int buf = it & 1;
        CPWAIT0();
        __syncthreads();   // also orders: all reads of buf (prev it) before this prefetch
        if (it < 15) {
            unsigned sd = (unsigned)__cvta_generic_to_shared(&Bsm[buf ^ 1][0]);
            const uint4* src = Bp + (it + 1) * 1024;
#pragma unroll
            for (int i = 0; i < 8; i++)
                CP16(sd + (tid + 128 * i) * 16, src + tid + 128 * i);
            CPCOMMIT();
        }

        const uint4* Bb = &Bsm[buf][0];
        uint4 bf = Bb[lane];   // register prefetch of B fragment group j=0
#pragma unroll
        for (int nb = 0; nb < 8; nb++) {
            // (1) merge previous nb's chains into saved regs (results long ready)
            if (it + nb > 0) {
                csv[0] = eA0 + oA0; csv[1] = eA1 + oA1;
                csv[2] = eA2 + oA2; csv[3] = eA3 + oA3;
                csv[4] = eB0 + oB0; csv[5] = eB1 + oB1;
                csv[6] = eB2 + oB2; csv[7] = eB3 + oB3;
            }
            // (2) issue this nb's 16 mmas, prefetching the next B fragment group
            eA0=0.f;eA1=0.f;eA2=0.f;eA3=0.f; oA0=0.f;oA1=0.f;oA2=0.f;oA3=0.f;
            eB0=0.f;eB1=0.f;eB2=0.f;eB3=0.f; oB0=0.f;oB1=0.f;oB2=0.f;oB3=0.f;
#pragma unroll
            for (int s2 = 0; s2 < 4; s2++) {
                uint4 bcur = bf;
                if (nb * 4 + s2 < 31)
                    bf = Bb[(nb * 4 + s2 + 1) * 32 + lane];
                MMA_BF16(eA0, eA1, eA2, eA3, a0[2 * s2],     bcur.x, bcur.y);
                MMA_BF16(eB0, eB1, eB2, eB3, a1[2 * s2],     bcur.x, bcur.y);
                MMA_BF16(oA0, oA1, oA2, oA3, a0[2 * s2 + 1], bcur.z, bcur.w);
                MMA_BF16(oB0, oB1, oB2, oB3, a1[2 * s2 + 1], bcur.z, bcur.w);
            }
            // (3) epilogue for the previous nb while these mmas are in flight
            if (it + nb > 0) EPILOGUE(csv, lcp);
            // (4) capture this nb's column labels for next round
            lcp = ((const int2*)labsm)[it * 32 + nb * 4 + tig];
        }
        // no trailing barrier: next iteration's leading __syncthreads orders
        // these buf reads before the prefetch that overwrites buf.
    }

    // drain: merge + epilogue for the final nb
    csv[0] = eA0 + oA0; csv[1] = eA1 + oA1;
    csv[2] = eA2 + oA2; csv[3] = eA3 + oA3;
    csv[4] = eB0 + oB0; csv[5] = eB1 + oB1;
    csv[6] = eB2 + oB2; csv[7] = eB3 + oB3;
    EPILOGUE(csv, lcp);

    // unpack packed accumulators
    float sa, sb;
    asm("mov.b64 {%0,%1},%2;" : "=f"(sa), "=f"(sb) : "l"(sxp));  float sxw = sa + sb;
    asm("mov.b64 {%0,%1},%2;" : "=f"(sa), "=f"(sb) : "l"(sep0)); float se0 = sa + sb;
    asm("mov.b64 {%0,%1},%2;" : "=f"(sa), "=f"(sb) : "l"(sep1)); float se1 = sa + sb;
    asm("mov.b64 {%0,%1},%2;" : "=f"(sa), "=f"(sb) : "l"(sep2)); float se2 = sa + sb;
    asm("mov.b64 {%0,%1},%2;" : "=f"(sa), "=f"(sb) : "l"(sep3)); float se3 = sa + sb;

    // per-row exp sums: reduce across the 4 lanes sharing each row
#pragma unroll
    for (int o = 1; o <= 2; o <<= 1) {
        se0 += __shfl_xor_sync(~0u, se0, o);
        se1 += __shfl_xor_sync(~0u, se1, o);
        se2 += __shfl_xor_sync(~0u, se2, o);
        se3 += __shfl_xor_sync(~0u, se3, o);
    }

    float v = 0.f;
    if (tig == 0) {
        float p0 = g_posl2[b * NPIX + r0];
        float p1 = g_posl2[b * NPIX + r0 + 8];
        float p2 = g_posl2[b * NPIX + r0 + 16];
        float p3 = g_posl2[b * NPIX + r0 + 24];
        float t0 = se0 + exp2p(p0);
        float t1 = se1 + exp2p(p1);
        float t2 = se2 + exp2p(p2);
        float t3 = se3 + exp2p(p3);
        v = (__log2f(t0) + __log2f(t1) + __log2f(t2) + __log2f(t3))
            - (p0 + p1 + p2 + p3) * (1.0f / 1025.0f);
    }
    v -= sxw * (1.0f / 1025.0f / 32.0f);   // spread warp-global sx over 32 lanes
#pragma unroll
    for (int o = 16; o; o >>= 1) v += __shfl_xor_sync(~0u, v, o);
    if (lane == 0) warpsum[w] = LN2F * v;
    __syncthreads();
    if (tid == 0) {
        float ts = warpsum[0] + warpsum[1] + warpsum[2] + warpsum[3];
        atomicAdd(&g_acc, (double)ts);
        __threadfence();
        unsigned done = atomicAdd(&g_done, 1u) + 1u;
        if (done == gridDim.x * gridDim.y) {
            double total = atomicAdd(&g_acc, 0.0);   // coherent read after all adds
            out[0] = (float)(total / (double)(BATCH * NPIX));
        }
    }
}

// ---------------- launch ----------------
extern "C" void kernel_launch(void* const* d_in, const int* in_sizes, int n_in,
                              void* d_out, int out_size) {
    const float* z1     = (const float*)d_in[0];
    const float* z2     = (const float*)d_in[1];
    const int*   labels = (const int*)d_in[2];
    (void)in_sizes; (void)n_in; (void)out_size;

    dim3 g1(NPIX / 32, BATCH);
    k_norm_pack<<<g1, 256>>>(z1, z2);
    k_packB<<<128, 256>>>(z2);
    dim3 g2(NPIX / 128, BATCH);
    k_main<<<g2, 128>>>(labels, (float*)d_out);
}

// round 14
// speedup vs baseline: 1.2429x; 1.0436x over previous
#include <cuda_runtime.h>
#include <cuda_bf16.h>
#include <cstdint>

// Problem constants (fixed shapes)
#define BATCH 2
#define CDIM 128
#define NPIX 65536          // 256*256
#define LAST0 64512         // (chunks-1)*M
#define NROWBLK 4096        // NPIX/16
#define SCALE_L2 20.6099075f   // 1/(0.07 * ln2)
#define LN2F 0.6931471805599453f

typedef unsigned long long u64;

// ---------------- scratch (device globals: no allocations allowed) ----------
__device__ uint4    g_Apack[BATCH * NROWBLK * 8 * 32];   // 33.5 MB, bf16 mma A fragments
__device__ uint4    g_Bpack[BATCH * 16 * 1024];          // 512 KB: [b][it][(nb*4+s2)*32+lane]
__device__ float    g_inv2[BATCH * NPIX];
__device__ float    g_posl2[BATCH * NPIX];               // pos logit in log2 domain
__device__ double   g_acc;
__device__ unsigned g_done;

// ---------------- helpers ----------------
__device__ __forceinline__ unsigned pack2(float lo, float hi) {
    __nv_bfloat162 h = __floats2bfloat162_rn(lo, hi);
    return *reinterpret_cast<unsigned*>(&h);
}
__device__ __forceinline__ float ex2(float x) {
    float e; asm("ex2.approx.f32 %0,%1;" : "=f"(e) : "f"(x)); return e;
}

#define CP16(dst, src) asm volatile("cp.async.ca.shared.global [%0],[%1],16;\n" :: "r"(dst), "l"(src))
#define CPCOMMIT()     asm volatile("cp.async.commit_group;\n")
#define CPWAIT0()      asm volatile("cp.async.wait_group 0;\n")

#define MMA_BF16(c0, c1, c2, c3, av, b0, b1)                               \
    asm volatile(                                                           \
        "mma.sync.aligned.m16n8k16.row.col.f32.bf16.bf16.f32 "             \
        "{%0,%1,%2,%3}, {%4,%5,%6,%7}, {%8,%9}, {%0,%1,%2,%3};\n"          \
        : "+f"(c0), "+f"(c1), "+f"(c2), "+f"(c3)                            \
        : "r"((av).x), "r"((av).y), "r"((av).z), "r"((av).w),               \
          "r"(b0), "r"(b1))

// epilogue on saved (already merged) results c[8] with label pair lcp.
// MUFU ex2.approx for the exp sums (exact 1.0 at masked-out x==0).
#define EPILOGUE(c, lcp) do {                                               \
    float v0 = (lr0 != (lcp).x) ? (c)[0] : 0.f;                             \
    float v1 = (lr0 != (lcp).y) ? (c)[1] : 0.f;                             \
    float v2 = (lr1 != (lcp).x) ? (c)[2] : 0.f;                             \
    float v3 = (lr1 != (lcp).y) ? (c)[3] : 0.f;                             \
    float v4 = (lr2 != (lcp).x) ? (c)[4] : 0.f;                             \
    float v5 = (lr2 != (lcp).y) ? (c)[5] : 0.f;                             \
    float v6 = (lr3 != (lcp).x) ? (c)[6] : 0.f;                             \
    float v7 = (lr3 != (lcp).y) ? (c)[7] : 0.f;                             \
    sxw += ((v0 + v1) + (v2 + v3)) + ((v4 + v5) + (v6 + v7));               \
    sep0 += ex2(v0) + ex2(v1);                                              \
    sep1 += ex2(v2) + ex2(v3);                                              \
    sep2 += ex2(v4) + ex2(v5);                                              \
    sep3 += ex2(v6) + ex2(v7);                                              \
} while (0)

// ---------------- kernel 1: normalize z1/z2, pos (fp32), pack A fragments ----------
__global__ void __launch_bounds__(256) k_norm_pack(const float* __restrict__ z1,
                                                   const float* __restrict__ z2) {
    if (blockIdx.x == 0 && blockIdx.y == 0 && threadIdx.x == 0) {
        g_acc = 0.0;
        g_done = 0u;
    }
    const int b  = blockIdx.y;
    const int p0 = blockIdx.x * 32;
    const int tx = threadIdx.x & 31;   // pixel within tile
    const int ty = threadIdx.x >> 5;   // channel group

    __shared__ float s1[128][33];
    __shared__ float red[3][8][32];
    __shared__ float invsm[32];

    const float* z1b = z1 + (size_t)b * CDIM * NPIX + p0;
    const float* z2b = z2 + (size_t)b * CDIM * NPIX + p0;

    float ss1 = 0.f, ss2 = 0.f, dt = 0.f;
#pragma unroll
    for (int j = 0; j < 16; j++) {
        int c = ty * 16 + j;
        float v1 = z1b[(size_t)c * NPIX + tx];
        float v2 = z2b[(size_t)c * NPIX + tx];
        ss1 = fmaf(v1, v1, ss1);
        ss2 = fmaf(v2, v2, ss2);
        dt  = fmaf(v1, v2, dt);
        s1[c][tx] = v1;
    }
    red[0][ty][tx] = ss1; red[1][ty][tx] = ss2; red[2][ty][tx] = dt;
    __syncthreads();

    if (ty == 0) {
        float a = 0.f, bb = 0.f, d = 0.f;
#pragma unroll
        for (int j = 0; j < 8; j++) { a += red[0][j][tx]; bb += red[1][j][tx]; d += red[2][j][tx]; }
        float inv1 = 1.f / fmaxf(sqrtf(a),  1e-12f);
        float inv2 = 1.f / fmaxf(sqrtf(bb), 1e-12f);
        invsm[tx] = inv1;
        g_inv2 [b * NPIX + p0 + tx] = inv2;
        g_posl2[b * NPIX + p0 + tx] = d * inv1 * inv2 * SCALE_L2;  // pos in log2 domain
    }
    __syncthreads();

    // Pack A into mma fragment order
#pragma unroll
    for (int q = 0; q < 2; q++) {
        int wi   = threadIdx.x + q * 256;
        int rbl  = wi >> 8;
        int rem  = wi & 255;
        int s    = rem >> 5;
        int lane = rem & 31;
        int gid  = lane >> 2, tig = lane & 3;
        int pl   = rbl * 16 + gid;
        int k0   = s * 16 + tig * 2;
        float i1 = invsm[pl], i2 = invsm[pl + 8];
        uint4 o;
        o.x = pack2(s1[k0    ][pl]     * i1, s1[k0 + 1][pl]     * i1);
        o.y = pack2(s1[k0    ][pl + 8] * i2, s1[k0 + 1][pl + 8] * i2);
        o.z = pack2(s1[k0 + 8][pl]     * i1, s1[k0 + 9][pl]     * i1);
        o.w = pack2(s1[k0 + 8][pl + 8] * i2, s1[k0 + 9][pl + 8] * i2);
        int rb = blockIdx.x * 2 + rbl;
        g_Apack[((b * NROWBLK + rb) * 8 + s) * 32 + lane] = o;
    }
}

// ---------------- kernel 2: pack B fragments as uint4 (2 k-steps per entry) --------
__global__ void __launch_bounds__(256) k_packB(const float* __restrict__ z2) {
    int g = blockIdx.x * 256 + threadIdx.x;       // 0..32767
    int b   = g >> 14;
    int r   = g & 16383;
    int it  = r >> 10;
    int idx = r & 1023;
    int nb  = idx >> 7;
    int s2  = (idx >> 5) & 3;
    int lane = idx & 31;
    int gid = lane >> 2, tig = lane & 3;
    int n  = nb * 8 + gid;
    int pq = LAST0 + it * 64 + n;
    float inv = g_inv2[b * NPIX + pq] * SCALE_L2;
    const float* zp = z2 + (size_t)b * CDIM * NPIX + pq;
    int k0 = s2 * 32 + tig * 2;
    uint4 o;
    o.x = pack2(zp[(size_t)(k0     ) * NPIX] * inv, zp[(size_t)(k0 +  1) * NPIX] * inv);
    o.y = pack2(zp[(size_t)(k0 +  8) * NPIX] * inv, zp[(size_t)(k0 +  9) * NPIX] * inv);
    o.z = pack2(zp[(size_t)(k0 + 16) * NPIX] * inv, zp[(size_t)(k0 + 17) * NPIX] * inv);
    o.w = pack2(zp[(size_t)(k0 + 24) * NPIX] * inv, zp[(size_t)(k0 + 25) * NPIX] * inv);
    g_Bpack[g] = o;
}

// ---------------- kernel 3: bf16 GEMM + MUFU epilogue + folded finalize -------------
__global__ void __launch_bounds__(128, 3) k_main(const int* __restrict__ labels,
                                                 float* __restrict__ out) {
    const int b    = blockIdx.y;
    const int row0 = blockIdx.x * 128;
    const int tid  = threadIdx.x;      // 0..127
    const int w    = tid >> 5;         // 0..3
    const int lane = tid & 31;
    const int gid  = lane >> 2, tig = lane & 3;

    __shared__ uint4 Bsm[2][1024];   // double-buffered 16KB B tiles
    __shared__ int   labsm[1024];
    __shared__ float warpsum[4];

    // labels of last chunk -> shared (vectorized, 128 threads x 2)
    {
        const uint4* lp = (const uint4*)(labels + b * NPIX + LAST0);
        ((uint4*)labsm)[tid]       = lp[tid];
        ((uint4*)labsm)[tid + 128] = lp[tid + 128];
    }

    // A fragments for this warp's 32 rows (2 rowblocks): 16 x uint4
    const int rb0 = blockIdx.x * 8 + w * 2;
    uint4 a0[8], a1[8];
    const uint4* Ap = g_Apack + ((size_t)(b * NROWBLK + rb0) * 8) * 32 + lane;
#pragma unroll
    for (int s = 0; s < 8; s++) { a0[s] = Ap[s * 32]; a1[s] = Ap[256 + s * 32]; }

    const int r0  = row0 + w * 32 + gid;
    const int lr0 = labels[b * NPIX + r0];
    const int lr1 = labels[b * NPIX + r0 + 8];
    const int lr2 = labels[b * NPIX + r0 + 16];
    const int lr3 = labels[b * NPIX + r0 + 24];

    float sxw  = 0.f;                                   // warp-thread sum of masked logits
    float sep0 = 0.f, sep1 = 0.f, sep2 = 0.f, sep3 = 0.f;  // per-row-pair exp sums

    // 4 independent mma chains + pipelined saved results
    float eA0=0.f,eA1=0.f,eA2=0.f,eA3=0.f, oA0=0.f,oA1=0.f,oA2=0.f,oA3=0.f;
    float eB0=0.f,eB1=0.f,eB2=0.f,eB3=0.f, oB0=0.f,oB1=0.f,oB2=0.f,oB3=0.f;
    float csv[8];
    int2  lcp = make_int2(0, 0);

    const uint4* Bp = g_Bpack + b * 16384;

    // prefetch tile 0 (1024 uint4 by 128 threads)
    {
        unsigned sd = (unsigned)__cvta_generic_to_shared(&Bsm[0][0]);
#pragma unroll
        for (int i = 0; i < 8; i++)
            CP16(sd + (tid + 128 * i) * 16, Bp + tid + 128 * i);
        CPCOMMIT();
    }

    for (int it = 0; it < 16; it++) {
        const int buf = it & 1;
        CPWAIT0();
        __syncthreads();   // also orders: all reads of buf (prev it) before this prefetch
        if (it < 15) {
            unsigned sd = (unsigned)__cvta_generic_to_shared(&Bsm[buf ^ 1][0]);
            const uint4* src = Bp + (it + 1) * 1024;
#pragma unroll
            for (int i = 0; i < 8; i++)
                CP16(sd + (tid + 128 * i) * 16, src + tid + 128 * i);
            CPCOMMIT();
        }

        const uint4* Bb = &Bsm[buf][0];
        uint4 bf = Bb[lane];   // register prefetch of B fragment group j=0
#pragma unroll
        for (int nb = 0; nb < 8; nb++) {
            // (1) merge previous nb's chains into saved regs (results long ready)
            if (it + nb > 0) {
                csv[0] = eA0 + oA0; csv[1] = eA1 + oA1;
                csv[2] = eA2 + oA2; csv[3] = eA3 + oA3;
                csv[4] = eB0 + oB0; csv[5] = eB1 + oB1;
                csv[6] = eB2 + oB2; csv[7] = eB3 + oB3;
            }
            // (2) issue this nb's 16 mmas, prefetching the next B fragment group
            eA0=0.f;eA1=0.f;eA2=0.f;eA3=0.f; oA0=0.f;oA1=0.f;oA2=0.f;oA3=0.f;
            eB0=0.f;eB1=0.f;eB2=0.f;eB3=0.f; oB0=0.f;oB1=0.f;oB2=0.f;oB3=0.f;
#pragma unroll
            for (int s2 = 0; s2 < 4; s2++) {
                uint4 bcur = bf;
                if (nb * 4 + s2 < 31)
                    bf = Bb[(nb * 4 + s2 + 1) * 32 + lane];
                MMA_BF16(eA0, eA1, eA2, eA3, a0[2 * s2],     bcur.x, bcur.y);
                MMA_BF16(eB0, eB1, eB2, eB3, a1[2 * s2],     bcur.x, bcur.y);
                MMA_BF16(oA0, oA1, oA2, oA3, a0[2 * s2 + 1], bcur.z, bcur.w);
                MMA_BF16(oB0, oB1, oB2, oB3, a1[2 * s2 + 1], bcur.z, bcur.w);
            }
            // (3) epilogue for the previous nb while these mmas are in flight
            if (it + nb > 0) EPILOGUE(csv, lcp);
            // (4) capture this nb's column labels for next round
            lcp = ((const int2*)labsm)[it * 32 + nb * 4 + tig];
        }
        // no trailing barrier: next iteration's leading __syncthreads orders
        // these buf reads before the prefetch that overwrites buf.
    }

    // drain: merge + epilogue for the final nb
    csv[0] = eA0 + oA0; csv[1] = eA1 + oA1;
    csv[2] = eA2 + oA2; csv[3] = eA3 + oA3;
    csv[4] = eB0 + oB0; csv[5] = eB1 + oB1;
    csv[6] = eB2 + oB2; csv[7] = eB3 + oB3;
    EPILOGUE(csv, lcp);

    // per-row exp sums: reduce across the 4 lanes sharing each row
#pragma unroll
    for (int o = 1; o <= 2; o <<= 1) {
        sep0 += __shfl_xor_sync(~0u, sep0, o);
        sep1 += __shfl_xor_sync(~0u, sep1, o);
        sep2 += __shfl_xor_sync(~0u, sep2, o);
        sep3 += __shfl_xor_sync(~0u, sep3, o);
    }

    float v = 0.f;
    if (tig == 0) {
        float p0 = g_posl2[b * NPIX + r0];
        float p1 = g_posl2[b * NPIX + r0 + 8];
        float p2 = g_posl2[b * NPIX + r0 + 16];
        float p3 = g_posl2[b * NPIX + r0 + 24];
        float t0 = sep0 + ex2(p0);
        float t1 = sep1 + ex2(p1);
        float t2 = sep2 + ex2(p2);
        float t3 = sep3 + ex2(p3);
        v = (__log2f(t0) + __log2f(t1) + __log2f(t2) + __log2f(t3))
            - (p0 + p1 + p2 + p3) * (1.0f / 1025.0f);
    }
    v -= sxw * (1.0f / 1025.0f);   // per-thread sum of masked logits
#pragma unroll
    for (int o = 16; o; o >>= 1) v += __shfl_xor_sync(~0u, v, o);
    if (lane == 0) warpsum[w] = LN2F * v;
    __syncthreads();
    if (tid == 0) {
        float ts = warpsum[0] + warpsum[1] + warpsum[2] + warpsum[3];
        atomicAdd(&g_acc, (double)ts);
        __threadfence();
        unsigned done = atomicAdd(&g_done, 1u) + 1u;
        if (done == gridDim.x * gridDim.y) {
            double total = atomicAdd(&g_acc, 0.0);   // coherent read after all adds
            out[0] = (float)(total / (double)(BATCH * NPIX));
        }
    }
}

// ---------------- launch ----------------
extern "C" void kernel_launch(void* const* d_in, const int* in_sizes, int n_in,
                              void* d_out, int out_size) {
    const float* z1     = (const float*)d_in[0];
    const float* z2     = (const float*)d_in[1];
    const int*   labels = (const int*)d_in[2];
    (void)in_sizes; (void)n_in; (void)out_size;

    dim3 g1(NPIX / 32, BATCH);
    k_norm_pack<<<g1, 256>>>(z1, z2);
    k_packB<<<128, 256>>>(z2);
    dim3 g2(NPIX / 128, BATCH);
    k_main<<<g2, 128>>>(labels, (float*)d_out);
}

// round 15
// speedup vs baseline: 1.3028x; 1.0482x over previous
#include <cuda_runtime.h>
#include <cuda_bf16.h>
#include <cstdint>

// Problem constants (fixed shapes)
#define BATCH 2
#define CDIM 128
#define NPIX 65536          // 256*256
#define LAST0 64512         // (chunks-1)*M
#define NROWBLK 4096        // NPIX/16
#define SCALE_L2 20.6099075f   // 1/(0.07 * ln2)
#define LN2F 0.6931471805599453f

typedef unsigned long long u64;

// ---------------- scratch (device globals: no allocations allowed) ----------
__device__ uint4    g_Apack[BATCH * NROWBLK * 8 * 32];   // 33.5 MB, bf16 mma A fragments
__device__ uint4    g_Bpack[BATCH * 16 * 1024];          // 512 KB: [b][it][(nb*4+s2)*32+lane]
__device__ float    g_inv2[BATCH * NPIX];
__device__ float    g_posl2[BATCH * NPIX];               // pos logit in log2 domain
__device__ double   g_acc;
__device__ unsigned g_done;

// ---------------- helpers ----------------
__device__ __forceinline__ unsigned pack2(float lo, float hi) {
    __nv_bfloat162 h = __floats2bfloat162_rn(lo, hi);
    return *reinterpret_cast<unsigned*>(&h);
}
__device__ __forceinline__ float ex2(float x) {
    float e; asm("ex2.approx.f32 %0,%1;" : "=f"(e) : "f"(x)); return e;
}
// unpack bf16x2, scale both halves by f (fp32), repack
__device__ __forceinline__ unsigned scl2(unsigned u, float f) {
    float lo = __int_as_float(u << 16) * f;
    float hi = __int_as_float(u & 0xFFFF0000u) * f;
    return pack2(lo, hi);
}

#define CP16(dst, src) asm volatile("cp.async.ca.shared.global [%0],[%1],16;\n" :: "r"(dst), "l"(src))
#define CPCOMMIT()     asm volatile("cp.async.commit_group;\n")
#define CPWAIT0()      asm volatile("cp.async.wait_group 0;\n")

#define MMA_BF16(c0, c1, c2, c3, av, b0, b1)                               \
    asm volatile(                                                           \
        "mma.sync.aligned.m16n8k16.row.col.f32.bf16.bf16.f32 "             \
        "{%0,%1,%2,%3}, {%4,%5,%6,%7}, {%8,%9}, {%0,%1,%2,%3};\n"          \
        : "+f"(c0), "+f"(c1), "+f"(c2), "+f"(c3)                            \
        : "r"((av).x), "r"((av).y), "r"((av).z), "r"((av).w),               \
          "r"(b0), "r"(b1))

// epilogue on saved (already merged) results c[8] with label pair lcp.
// MUFU ex2.approx for the exp sums (exact 1.0 at masked-out x==0).
#define EPILOGUE(c, lcp) do {                                               \
    float v0 = (lr0 != (lcp).x) ? (c)[0] : 0.f;                             \
    float v1 = (lr0 != (lcp).y) ? (c)[1] : 0.f;                             \
    float v2 = (lr1 != (lcp).x) ? (c)[2] : 0.f;                             \
    float v3 = (lr1 != (lcp).y) ? (c)[3] : 0.f;                             \
    float v4 = (lr2 != (lcp).x) ? (c)[4] : 0.f;                             \
    float v5 = (lr2 != (lcp).y) ? (c)[5] : 0.f;                             \
    float v6 = (lr3 != (lcp).x) ? (c)[6] : 0.f;                             \
    float v7 = (lr3 != (lcp).y) ? (c)[7] : 0.f;                             \
    sxw += ((v0 + v1) + (v2 + v3)) + ((v4 + v5) + (v6 + v7));               \
    sep0 += ex2(v0) + ex2(v1);                                              \
    sep1 += ex2(v2) + ex2(v3);                                              \
    sep2 += ex2(v4) + ex2(v5);                                              \
    sep3 += ex2(v6) + ex2(v7);                                              \
} while (0)

// ---------------- kernel 1: normalize z1/z2 (vectorized), pos, pack A fragments -----
// 128-pixel x 128-channel tiles; all global loads are float4 along the pixel dim.
__global__ void __launch_bounds__(256) k_norm_pack(const float* __restrict__ z1,
                                                   const float* __restrict__ z2) {
    if (blockIdx.x == 0 && blockIdx.y == 0 && threadIdx.x == 0) {
        g_acc = 0.0;
        g_done = 0u;
    }
    const int b   = blockIdx.y;
    const int p0  = blockIdx.x * 128;
    const int tid = threadIdx.x;
    const int pg  = tid & 31;    // pixel group: pixels p0 + pg*4 .. +3
    const int cg  = tid >> 5;    // channel group: channels cg*16 .. +15

    __shared__ unsigned s1u[64][136];    // raw z1 bf16x2 pairs [ch-pair][pixel]
    __shared__ float    red[3][8][132];  // per-cg partial ss1/ss2/dot per pixel
    __shared__ float    invsm[128];

    const size_t base = (size_t)b * CDIM * NPIX + p0 + pg * 4;

    float4 ss1 = make_float4(0.f, 0.f, 0.f, 0.f);
    float4 ss2 = make_float4(0.f, 0.f, 0.f, 0.f);
    float4 dt  = make_float4(0.f, 0.f, 0.f, 0.f);
#pragma unroll
    for (int jp = 0; jp < 8; jp++) {
        int c0 = cg * 16 + jp * 2;
        float4 u0 = *(const float4*)(z1 + base + (size_t)(c0    ) * NPIX);
        float4 u1 = *(const float4*)(z1 + base + (size_t)(c0 + 1) * NPIX);
        float4 w0 = *(const float4*)(z2 + base + (size_t)(c0    ) * NPIX);
        float4 w1 = *(const float4*)(z2 + base + (size_t)(c0 + 1) * NPIX);
        ss1.x = fmaf(u0.x, u0.x, ss1.x); ss1.x = fmaf(u1.x, u1.x, ss1.x);
        ss1.y = fmaf(u0.y, u0.y, ss1.y); ss1.y = fmaf(u1.y, u1.y, ss1.y);
        ss1.z = fmaf(u0.z, u0.z, ss1.z); ss1.z = fmaf(u1.z, u1.z, ss1.z);
        ss1.w = fmaf(u0.w, u0.w, ss1.w); ss1.w = fmaf(u1.w, u1.w, ss1.w);
        ss2.x = fmaf(w0.x, w0.x, ss2.x); ss2.x = fmaf(w1.x, w1.x, ss2.x);
        ss2.y = fmaf(w0.y, w0.y, ss2.y); ss2.y = fmaf(w1.y, w1.y, ss2.y);
        ss2.z = fmaf(w0.z, w0.z, ss2.z); ss2.z = fmaf(w1.z, w1.z, ss2.z);
        ss2.w = fmaf(w0.w, w0.w, ss2.w); ss2.w = fmaf(w1.w, w1.w, ss2.w);
        dt.x  = fmaf(u0.x, w0.x, dt.x);  dt.x  = fmaf(u1.x, w1.x, dt.x);
        dt.y  = fmaf(u0.y, w0.y, dt.y);  dt.y  = fmaf(u1.y, w1.y, dt.y);
        dt.z  = fmaf(u0.z, w0.z, dt.z);  dt.z  = fmaf(u1.z, w1.z, dt.z);
        dt.w  = fmaf(u0.w, w0.w, dt.w);  dt.w  = fmaf(u1.w, w1.w, dt.w);
        uint4 o;
        o.x = pack2(u0.x, u1.x);
        o.y = pack2(u0.y, u1.y);
        o.z = pack2(u0.z, u1.z);
        o.w = pack2(u0.w, u1.w);
        *(uint4*)&s1u[cg * 8 + jp][pg * 4] = o;
    }
    *(float4*)&red[0][cg][pg * 4] = ss1;
    *(float4*)&red[1][cg][pg * 4] = ss2;
    *(float4*)&red[2][cg][pg * 4] = dt;
    __syncthreads();

    if (tid < 128) {
        float a = 0.f, bb = 0.f, d = 0.f;
#pragma unroll
        for (int g = 0; g < 8; g++) {
            a += red[0][g][tid]; bb += red[1][g][tid]; d += red[2][g][tid];
        }
        float inv1 = 1.f / fmaxf(sqrtf(a),  1e-12f);
        float inv2 = 1.f / fmaxf(sqrtf(bb), 1e-12f);
        invsm[tid] = inv1;
        g_inv2 [b * NPIX + p0 + tid] = inv2;
        g_posl2[b * NPIX + p0 + tid] = d * inv1 * inv2 * SCALE_L2;  // pos in log2 domain
    }
    __syncthreads();

    // Pack A into mma fragment order: 2048 uint4 per tile by 256 threads.
#pragma unroll
    for (int q = 0; q < 8; q++) {
        int wi   = tid + 256 * q;        // 0..2047
        int rbl  = wi >> 8;              // rowblock 0..7
        int rem  = wi & 255;
        int s    = rem >> 5;             // k-step 0..7
        int lane = rem & 31;
        int gid  = lane >> 2, tig = lane & 3;
        int pl   = rbl * 16 + gid;
        int k2   = s * 8 + tig;          // bf16-pair index of k0 = s*16 + tig*2
        float i1 = invsm[pl], i2 = invsm[pl + 8];
        uint4 o;
        o.x = scl2(s1u[k2    ][pl    ], i1);
        o.y = scl2(s1u[k2    ][pl + 8], i2);
        o.z = scl2(s1u[k2 + 4][pl    ], i1);
        o.w = scl2(s1u[k2 + 4][pl + 8], i2);
        int rb = blockIdx.x * 8 + rbl;
        g_Apack[((b * NROWBLK + rb) * 8 + s) * 32 + lane] = o;
    }
}

// ---------------- kernel 2: pack B fragments as uint4 (2 k-steps per entry) --------
__global__ void __launch_bounds__(256) k_packB(const float* __restrict__ z2) {
    int g = blockIdx.x * 256 + threadIdx.x;       // 0..32767
    int b   = g >> 14;
    int r   = g & 16383;
    int it  = r >> 10;
    int idx = r & 1023;
    int nb  = idx >> 7;
    int s2  = (idx >> 5) & 3;
    int lane = idx & 31;
    int gid = lane >> 2, tig = lane & 3;
    int n  = nb * 8 + gid;
    int pq = LAST0 + it * 64 + n;
    float inv = g_inv2[b * NPIX + pq] * SCALE_L2;
    const float* zp = z2 + (size_t)b * CDIM * NPIX + pq;
    int k0 = s2 * 32 + tig * 2;
    uint4 o;
    o.x = pack2(zp[(size_t)(k0     ) * NPIX] * inv, zp[(size_t)(k0 +  1) * NPIX] * inv);
    o.y = pack2(zp[(size_t)(k0 +  8) * NPIX] * inv, zp[(size_t)(k0 +  9) * NPIX] * inv);
    o.z = pack2(zp[(size_t)(k0 + 16) * NPIX] * inv, zp[(size_t)(k0 + 17) * NPIX] * inv);
    o.w = pack2(zp[(size_t)(k0 + 24) * NPIX] * inv, zp[(size_t)(k0 + 25) * NPIX] * inv);
    g_Bpack[g] = o;
}

// ---------------- kernel 3: bf16 GEMM + MUFU epilogue + folded finalize -------------
__global__ void __launch_bounds__(128, 3) k_main(const int* __restrict__ labels,
                                                 float* __restrict__ out) {
    const int b    = blockIdx.y;
    const int row0 = blockIdx.x * 128;
    const int tid  = threadIdx.x;      // 0..127
    const int w    = tid >> 5;         // 0..3
    const int lane = tid & 31;
    const int gid  = lane >> 2, tig = lane & 3;

    __shared__ uint4 Bsm[2][1024];   // double-buffered 16KB B tiles
    __shared__ int   labsm[1024];
    __shared__ float warpsum[4];

    // labels of last chunk -> shared (vectorized, 128 threads x 2)
    {
        const uint4* lp = (const uint4*)(labels + b * NPIX + LAST0);
        ((uint4*)labsm)[tid]       = lp[tid];
        ((uint4*)labsm)[tid + 128] = lp[tid + 128];
    }

    // A fragments for this warp's 32 rows (2 rowblocks): 16 x uint4
    const int rb0 = blockIdx.x * 8 + w * 2;
    uint4 a0[8], a1[8];
    const uint4* Ap = g_Apack + ((size_t)(b * NROWBLK + rb0) * 8) * 32 + lane;
#pragma unroll
    for (int s = 0; s < 8; s++) { a0[s] = Ap[s * 32]; a1[s] = Ap[256 + s * 32]; }

    const int r0  = row0 + w * 32 + gid;
    const int lr0 = labels[b * NPIX + r0];
    const int lr1 = labels[b * NPIX + r0 + 8];
    const int lr2 = labels[b * NPIX + r0 + 16];
    const int lr3 = labels[b * NPIX + r0 + 24];

    float sxw  = 0.f;                                   // per-thread sum of masked logits
    float sep0 = 0.f, sep1 = 0.f, sep2 = 0.f, sep3 = 0.f;  // per-row-pair exp sums

    // 4 independent mma chains + pipelined saved results
    float eA0=0.f,eA1=0.f,eA2=0.f,eA3=0.f, oA0=0.f,oA1=0.f,oA2=0.f,oA3=0.f;
    float eB0=0.f,eB1=0.f,eB2=0.f,eB3=0.f, oB0=0.f,oB1=0.f,oB2=0.f,oB3=0.f;
    float csv[8];
    int2  lcp = make_int2(0, 0);

    const uint4* Bp = g_Bpack + b * 16384;

    // prefetch tile 0 (1024 uint4 by 128 threads)
    {
        unsigned sd = (unsigned)__cvta_generic_to_shared(&Bsm[0][0]);
#pragma unroll
        for (int i = 0; i < 8; i++)
            CP16(sd + (tid + 128 * i) * 16, Bp + tid + 128 * i);
        CPCOMMIT();
    }

    for (int it = 0; it < 16; it++) {
        const int buf = it & 1;
        CPWAIT0();
        __syncthreads();   // also orders: all reads of buf (prev it) before this prefetch
        if (it < 15) {
            unsigned sd = (unsigned)__cvta_generic_to_shared(&Bsm[buf ^ 1][0]);
            const uint4* src = Bp + (it + 1) * 1024;
#pragma unroll
            for (int i = 0; i < 8; i++)
                CP16(sd + (tid + 128 * i) * 16, src + tid + 128 * i);
            CPCOMMIT();
        }

        const uint4* Bb = &Bsm[buf][0];
        uint4 bf = Bb[lane];   // register prefetch of B fragment group j=0
#pragma unroll
        for (int nb = 0; nb < 8; nb++) {
            // (1) merge previous nb's chains into saved regs (results long ready)
            if (it + nb > 0) {
                csv[0] = eA0 + oA0; csv[1] = eA1 + oA1;
                csv[2] = eA2 + oA2; csv[3] = eA3 + oA3;
                csv[4] = eB0 + oB0; csv[5] = eB1 + oB1;
                csv[6] = eB2 + oB2; csv[7] = eB3 + oB3;
            }
            // (2) issue this nb's 16 mmas, prefetching the next B fragment group
            eA0=0.f;eA1=0.f;eA2=0.f;eA3=0.f; oA0=0.f;oA1=0.f;oA2=0.f;oA3=0.f;
            eB0=0.f;eB1=0.f;eB2=0.f;eB3=0.f; oB0=0.f;oB1=0.f;oB2=0.f;oB3=0.f;
#pragma unroll
            for (int s2 = 0; s2 < 4; s2++) {
                uint4 bcur = bf;
                if (nb * 4 + s2 < 31)
                    bf = Bb[(nb * 4 + s2 + 1) * 32 + lane];
                MMA_BF16(eA0, eA1, eA2, eA3, a0[2 * s2],     bcur.x, bcur.y);
                MMA_BF16(eB0, eB1, eB2, eB3, a1[2 * s2],     bcur.x, bcur.y);
                MMA_BF16(oA0, oA1, oA2, oA3, a0[2 * s2 + 1], bcur.z, bcur.w);
                MMA_BF16(oB0, oB1, oB2, oB3, a1[2 * s2 + 1], bcur.z, bcur.w);
            }
            // (3) epilogue for the previous nb while these mmas are in flight
            if (it + nb > 0) EPILOGUE(csv, lcp);
            // (4) capture this nb's column labels for next round
            lcp = ((const int2*)labsm)[it * 32 + nb * 4 + tig];
        }
        // no trailing barrier: next iteration's leading __syncthreads orders
        // these buf reads before the prefetch that overwrites buf.
    }

    // drain: merge + epilogue for the final nb
    csv[0] = eA0 + oA0; csv[1] = eA1 + oA1;
    csv[2] = eA2 + oA2; csv[3] = eA3 + oA3;
    csv[4] = eB0 + oB0; csv[5] = eB1 + oB1;
    csv[6] = eB2 + oB2; csv[7] = eB3 + oB3;
    EPILOGUE(csv, lcp);

    // per-row exp sums: reduce across the 4 lanes sharing each row
#pragma unroll
    for (int o = 1; o <= 2; o <<= 1) {
        sep0 += __shfl_xor_sync(~0u, sep0, o);
        sep1 += __shfl_xor_sync(~0u, sep1, o);
        sep2 += __shfl_xor_sync(~0u, sep2, o);
        sep3 += __shfl_xor_sync(~0u, sep3, o);
    }

    float v = 0.f;
    if (tig == 0) {
        float p0 = g_posl2[b * NPIX + r0];
        float p1 = g_posl2[b * NPIX + r0 + 8];
        float p2 = g_posl2[b * NPIX + r0 + 16];
        float p3 = g_posl2[b * NPIX + r0 + 24];
        float t0 = sep0 + ex2(p0);
        float t1 = sep1 + ex2(p1);
        float t2 = sep2 + ex2(p2);
        float t3 = sep3 + ex2(p3);
        v = (__log2f(t0) + __log2f(t1) + __log2f(t2) + __log2f(t3))
            - (p0 + p1 + p2 + p3) * (1.0f / 1025.0f);
    }
    v -= sxw * (1.0f / 1025.0f);   // per-thread sum of masked logits
#pragma unroll
    for (int o = 16; o; o >>= 1) v += __shfl_xor_sync(~0u, v, o);
    if (lane == 0) warpsum[w] = LN2F * v;
    __syncthreads();
    if (tid == 0) {
        float ts = warpsum[0] + warpsum[1] + warpsum[2] + warpsum[3];
        atomicAdd(&g_acc, (double)ts);
        __threadfence();
        unsigned done = atomicAdd(&g_done, 1u) + 1u;
        if (done == gridDim.x * gridDim.y) {
            double total = atomicAdd(&g_acc, 0.0);   // coherent read after all adds
            out[0] = (float)(total / (double)(BATCH * NPIX));
        }
    }
}

// ---------------- launch ----------------
extern "C" void kernel_launch(void* const* d_in, const int* in_sizes, int n_in,
                              void* d_out, int out_size) {
    const float* z1     = (const float*)d_in[0];
    const float* z2     = (const float*)d_in[1];
    const int*   labels = (const int*)d_in[2];
    (void)in_sizes; (void)n_in; (void)out_size;

    dim3 g1(NPIX / 128, BATCH);
    k_norm_pack<<<g1, 256>>>(z1, z2);
    k_packB<<<128, 256>>>(z2);
    dim3 g2(NPIX / 128, BATCH);
    k_main<<<g2, 128>>>(labels, (float*)d_out);
}